// round 2
// baseline (speedup 1.0000x reference)
#include <cuda_runtime.h>
#include <cuda_bf16.h>

#define Bb   8
#define T    16
#define C    64
#define Hh   56
#define Ww   56
#define HW   3136          // 56*56
#define HW4  784           // HW/4
#define DIN  64            // 8*8 pooled
#define DOUT 32            // 2*d_t
#define NBC  512           // b*c

// att scratch: [n][t][s]
__device__ float g_att[NBC * T * T];

// ---------------------------------------------------------------------------
// Kernel A: per-(b,c) block. Pool 56x56 -> 8x8 per t, compute q,k,att,softmax.
// ---------------------------------------------------------------------------
__global__ __launch_bounds__(256)
void pool_att_kernel(const float* __restrict__ x,
                     const float* __restrict__ Wq, const float* __restrict__ bq,
                     const float* __restrict__ Wk, const float* __restrict__ bk)
{
    const int n   = blockIdx.x;        // n = b*C + c
    const int b   = n >> 6;
    const int c   = n & 63;
    const int tid = threadIdx.x;

    __shared__ float sx[HW];                 // one t-slice, 12.5 KB
    __shared__ float flat[T][DIN];           // pooled features
    __shared__ float sWq[DIN * DOUT];        // 8 KB
    __shared__ float sWk[DIN * DOUT];        // 8 KB
    __shared__ float sq[T][DOUT + 1];        // padded vs bank conflicts
    __shared__ float sk[T][DOUT + 1];
    __shared__ float satt[T][T + 1];

    // cache weights once
    for (int i = tid; i < DIN * DOUT; i += 256) {
        sWq[i] = Wq[i];
        sWk[i] = Wk[i];
    }

    // ---- pooling: for each t, stage slice in smem then reduce 7x7 bins ----
    for (int t = 0; t < T; ++t) {
        const float4* xp4 =
            (const float4*)(x + ((size_t)(b * T + t) * C + c) * HW);
        __syncthreads();                       // protect sx from prev reduce
        for (int i = tid; i < HW4; i += 256)
            ((float4*)sx)[i] = xp4[i];
        __syncthreads();
        if (tid < 64) {
            const int d1 = tid >> 3, d2 = tid & 7;
            const float* row = sx + (7 * d1) * Ww + 7 * d2;
            float s = 0.f;
            #pragma unroll
            for (int dh = 0; dh < 7; ++dh)
                #pragma unroll
                for (int dw = 0; dw < 7; ++dw)
                    s += row[dh * Ww + dw];
            flat[t][tid] = s * (1.f / 49.f);
        }
    }
    __syncthreads();

    // ---- q = flat@Wq + bq ; k = flat@Wk + bk   (T*DOUT = 512 outs each) ----
    for (int i = tid; i < T * DOUT; i += 256) {
        const int tt = i >> 5, j = i & 31;
        float aq = bq[j];
        float ak = bk[j];
        #pragma unroll
        for (int d = 0; d < DIN; ++d) {
            const float f = flat[tt][d];
            aq = fmaf(f, sWq[d * DOUT + j], aq);
            ak = fmaf(f, sWk[d * DOUT + j], ak);
        }
        sq[tt][j] = aq;
        sk[tt][j] = ak;
    }
    __syncthreads();

    // ---- att[i][j] = (q_i . k_j) / sqrt(T)   (256 entries, 1 per thread) --
    {
        const int i = tid >> 4, j = tid & 15;
        float s = 0.f;
        #pragma unroll
        for (int d = 0; d < DOUT; ++d)
            s = fmaf(sq[i][d], sk[j][d], s);
        satt[i][j] = s * 0.25f;                // 1/sqrt(16)
    }
    __syncthreads();

    // ---- row softmax + write to global ----
    if (tid < T) {
        const int i = tid;
        float m = -1e30f;
        #pragma unroll
        for (int j = 0; j < T; ++j) m = fmaxf(m, satt[i][j]);
        float e[T];
        float ssum = 0.f;
        #pragma unroll
        for (int j = 0; j < T; ++j) {
            e[j] = __expf(satt[i][j] - m);
            ssum += e[j];
        }
        const float inv = 1.f / ssum;
        #pragma unroll
        for (int j = 0; j < T; ++j)
            g_att[n * (T * T) + i * T + j] = e[j] * inv;
    }
}

// ---------------------------------------------------------------------------
// Kernel B: out[b,t,c,:] = sum_s att[n,t,s] * x[b,s,c,:]
// One float4 column per thread; 16 LDG.128 up front (MLP=16), 1024 FMA,
// 16 STG.128. Exactly one read + one write of the 103MB tensor.
// ---------------------------------------------------------------------------
__global__ __launch_bounds__(256)
void av_kernel(const float* __restrict__ x, float* __restrict__ out)
{
    const int n   = blockIdx.y;        // n = b*C + c
    const int b   = n >> 6;
    const int c   = n & 63;
    const int tid = threadIdx.x;

    __shared__ float satt[T][T];
    satt[tid >> 4][tid & 15] = g_att[n * (T * T) + tid];
    __syncthreads();

    const int p4 = blockIdx.x * 256 + tid;
    if (p4 >= HW4) return;

    const size_t stride_s = (size_t)C * HW4;           // float4 stride per t/s
    const float4* xb = (const float4*)x
                     + ((size_t)b * T * C + c) * HW4 + p4;
    float4* ob = (float4*)out
               + ((size_t)b * T * C + c) * HW4 + p4;

    float4 v[T];
    #pragma unroll
    for (int s = 0; s < T; ++s)
        v[s] = xb[s * stride_s];

    #pragma unroll
    for (int t = 0; t < T; ++t) {
        float4 a = make_float4(0.f, 0.f, 0.f, 0.f);
        #pragma unroll
        for (int s = 0; s < T; ++s) {
            const float w = satt[t][s];
            a.x = fmaf(w, v[s].x, a.x);
            a.y = fmaf(w, v[s].y, a.y);
            a.z = fmaf(w, v[s].z, a.z);
            a.w = fmaf(w, v[s].w, a.w);
        }
        ob[t * stride_s] = a;
    }
}

// ---------------------------------------------------------------------------
extern "C" void kernel_launch(void* const* d_in, const int* in_sizes, int n_in,
                              void* d_out, int out_size)
{
    const float* x  = (const float*)d_in[0];
    const float* Wq = (const float*)d_in[1];
    const float* bq = (const float*)d_in[2];
    const float* Wk = (const float*)d_in[3];
    const float* bk = (const float*)d_in[4];
    float* out = (float*)d_out;

    pool_att_kernel<<<NBC, 256>>>(x, Wq, bq, Wk, bk);
    av_kernel<<<dim3((HW4 + 255) / 256, NBC), 256>>>(x, out);
}

// round 3
// speedup vs baseline: 2.5030x; 2.5030x over previous
#include <cuda_runtime.h>
#include <cuda_bf16.h>

#define Bb   8
#define T    16
#define C    64
#define Hh   56
#define Ww   56
#define HW   3136          // 56*56
#define HW4  784           // HW/4
#define DIN  64            // 8*8 pooled
#define DOUT 32            // 2*d_t
#define NBC  512           // b*c
#define NT   (NBC * T)     // 8192 (n,t) slices

// scratch
__device__ float g_flat[NT * DIN];       // pooled features [n*T+t][64], 2MB
__device__ float g_att[NBC * T * T];     // softmaxed attention, 512KB

// ---------------------------------------------------------------------------
// Kernel 1: pooling. One block per (n,t) slice: 56x56 -> 8x8 (7x7 mean bins).
// 8192 blocks -> the full 103MB read is exposed in parallel.
// ---------------------------------------------------------------------------
__global__ __launch_bounds__(256)
void pool_kernel(const float* __restrict__ x)
{
    const int nt  = blockIdx.x;        // n*T + t
    const int n   = nt >> 4;
    const int t   = nt & 15;
    const int b   = n >> 6;
    const int c   = n & 63;
    const int tid = threadIdx.x;

    __shared__ float sx[HW];           // 12.5 KB

    const float4* xp4 =
        (const float4*)(x + ((size_t)(b * T + t) * C + c) * HW);
    #pragma unroll
    for (int i = tid; i < HW4; i += 256)
        ((float4*)sx)[i] = xp4[i];
    __syncthreads();

    if (tid < 64) {
        const int d1 = tid >> 3, d2 = tid & 7;
        const float* row = sx + (7 * d1) * Ww + 7 * d2;
        float s = 0.f;
        #pragma unroll
        for (int dh = 0; dh < 7; ++dh)
            #pragma unroll
            for (int dw = 0; dw < 7; ++dw)
                s += row[dh * Ww + dw];
        g_flat[nt * DIN + tid] = s * (1.f / 49.f);
    }
}

// ---------------------------------------------------------------------------
// Kernel 2: q/k projection + att + softmax. One block per n. Tiny.
// ---------------------------------------------------------------------------
__global__ __launch_bounds__(256)
void att_kernel(const float* __restrict__ Wq, const float* __restrict__ bq,
                const float* __restrict__ Wk, const float* __restrict__ bk)
{
    const int n   = blockIdx.x;
    const int tid = threadIdx.x;

    __shared__ float flat[T][DIN];           // 4 KB
    __shared__ float sWq[DIN * DOUT];        // 8 KB
    __shared__ float sWk[DIN * DOUT];        // 8 KB
    __shared__ float sq[T][DOUT + 1];
    __shared__ float sk[T][DOUT + 1];
    __shared__ float satt[T][T + 1];

    for (int i = tid; i < DIN * DOUT; i += 256) {
        sWq[i] = Wq[i];
        sWk[i] = Wk[i];
    }
    for (int i = tid; i < T * DIN; i += 256)
        ((float*)flat)[i] = g_flat[n * T * DIN + i];
    __syncthreads();

    // q = flat@Wq + bq ; k = flat@Wk + bk  (T*DOUT = 512 outs each, 2/thread)
    for (int i = tid; i < T * DOUT; i += 256) {
        const int tt = i >> 5, j = i & 31;
        float aq = bq[j];
        float ak = bk[j];
        #pragma unroll
        for (int d = 0; d < DIN; ++d) {
            const float f = flat[tt][d];
            aq = fmaf(f, sWq[d * DOUT + j], aq);
            ak = fmaf(f, sWk[d * DOUT + j], ak);
        }
        sq[tt][j] = aq;
        sk[tt][j] = ak;
    }
    __syncthreads();

    // att[i][j] = (q_i . k_j) / sqrt(T)
    {
        const int i = tid >> 4, j = tid & 15;
        float s = 0.f;
        #pragma unroll
        for (int d = 0; d < DOUT; ++d)
            s = fmaf(sq[i][d], sk[j][d], s);
        satt[i][j] = s * 0.25f;                // 1/sqrt(16)
    }
    __syncthreads();

    // row softmax -> g_att
    if (tid < T) {
        const int i = tid;
        float m = -1e30f;
        #pragma unroll
        for (int j = 0; j < T; ++j) m = fmaxf(m, satt[i][j]);
        float e[T];
        float ssum = 0.f;
        #pragma unroll
        for (int j = 0; j < T; ++j) {
            e[j] = __expf(satt[i][j] - m);
            ssum += e[j];
        }
        const float inv = 1.f / ssum;
        #pragma unroll
        for (int j = 0; j < T; ++j)
            g_att[n * (T * T) + i * T + j] = e[j] * inv;
    }
}

// ---------------------------------------------------------------------------
// Kernel 3: out[b,t,c,:] = sum_s att[n,t,s] * x[b,s,c,:]
// One float4 column per thread; 16 LDG.128 (MLP=16), 1024 FMA, 16 streaming
// STG.128 (__stcs keeps x resident in L2 for the re-read).
// ---------------------------------------------------------------------------
__global__ __launch_bounds__(256)
void av_kernel(const float* __restrict__ x, float* __restrict__ out)
{
    const int n   = blockIdx.y;        // n = b*C + c
    const int b   = n >> 6;
    const int c   = n & 63;
    const int tid = threadIdx.x;

    __shared__ float satt[T][T];
    satt[tid >> 4][tid & 15] = g_att[n * (T * T) + tid];
    __syncthreads();

    const int p4 = blockIdx.x * 256 + tid;
    if (p4 >= HW4) return;

    const size_t stride_s = (size_t)C * HW4;           // float4 stride per t/s
    const float4* xb = (const float4*)x
                     + ((size_t)b * T * C + c) * HW4 + p4;
    float4* ob = (float4*)out
               + ((size_t)b * T * C + c) * HW4 + p4;

    float4 v[T];
    #pragma unroll
    for (int s = 0; s < T; ++s)
        v[s] = xb[s * stride_s];

    #pragma unroll
    for (int t = 0; t < T; ++t) {
        float4 a = make_float4(0.f, 0.f, 0.f, 0.f);
        #pragma unroll
        for (int s = 0; s < T; ++s) {
            const float w = satt[t][s];
            a.x = fmaf(w, v[s].x, a.x);
            a.y = fmaf(w, v[s].y, a.y);
            a.z = fmaf(w, v[s].z, a.z);
            a.w = fmaf(w, v[s].w, a.w);
        }
        __stcs(&ob[t * stride_s], a);      // streaming store: don't evict x
    }
}

// ---------------------------------------------------------------------------
extern "C" void kernel_launch(void* const* d_in, const int* in_sizes, int n_in,
                              void* d_out, int out_size)
{
    const float* x  = (const float*)d_in[0];
    const float* Wq = (const float*)d_in[1];
    const float* bq = (const float*)d_in[2];
    const float* Wk = (const float*)d_in[3];
    const float* bk = (const float*)d_in[4];
    float* out = (float*)d_out;

    pool_kernel<<<NT, 256>>>(x);
    att_kernel<<<NBC, 256>>>(Wq, bq, Wk, bk);
    av_kernel<<<dim3((HW4 + 255) / 256, NBC), 256>>>(x, out);
}